// round 13
// baseline (speedup 1.0000x reference)
#include <cuda_runtime.h>
#include <cuda_fp16.h>
#include <cstdint>

#define NPTS 262144

// ---------------- device scratch (no allocations allowed) ----------------
__device__ __half d_h2h [NPTS * 64];      // after mlp1+mlp2 (relu, fp16)
__device__ __half d_xgmh[NPTS * 64];      // neighbor max-pooled (fp16)
__device__ __half d_h4h [NPTS * 128];     // after mlp3+mlp4 (relu, fp16)
__device__ __half d_w2h [64 * 64];
__device__ __half d_w3h [64 * 64];
__device__ __half d_w4h [128 * 64];
__device__ __half d_w5h [1024 * 192];
__device__ float  d_g  [1024];            // global max (post-relu), atomicMax target
__device__ float  d_f1 [512];
__device__ float  d_f2 [256];

// ---------------- helpers ----------------
__device__ __forceinline__ uint32_t smem_u32(const void* p) {
    uint32_t a;
    asm("{ .reg .u64 t; cvta.to.shared.u64 t, %1; cvt.u32.u64 %0, t; }"
        : "=r"(a) : "l"(p));
    return a;
}
__device__ __forceinline__ void cp16(uint32_t dst, const void* src) {
    asm volatile("cp.async.cg.shared.global [%0], [%1], 16;"
                 :: "r"(dst), "l"(src) : "memory");
}
#define CP_COMMIT() asm volatile("cp.async.commit_group;" ::: "memory")
#define CP_WAIT0()  asm volatile("cp.async.wait_group 0;" ::: "memory")

__device__ __forceinline__ void ldsm4(uint32_t& r0, uint32_t& r1,
                                      uint32_t& r2, uint32_t& r3, uint32_t addr) {
    asm volatile("ldmatrix.sync.aligned.m8n8.x4.shared.b16 {%0,%1,%2,%3}, [%4];"
                 : "=r"(r0), "=r"(r1), "=r"(r2), "=r"(r3) : "r"(addr));
}
__device__ __forceinline__ void mma_f16(float* c, uint32_t a0, uint32_t a1,
                                        uint32_t a2, uint32_t a3,
                                        uint32_t b0, uint32_t b1) {
    asm volatile(
        "mma.sync.aligned.m16n8k16.row.col.f32.f16.f16.f32 "
        "{%0,%1,%2,%3}, {%4,%5,%6,%7}, {%8,%9}, {%0,%1,%2,%3};"
        : "+f"(c[0]), "+f"(c[1]), "+f"(c[2]), "+f"(c[3])
        : "r"(a0), "r"(a1), "r"(a2), "r"(a3), "r"(b0), "r"(b1));
}
__device__ __forceinline__ uint32_t ph2_relu(float x, float y) {
    __half2 h = __floats2half2_rn(fmaxf(x, 0.f), fmaxf(y, 0.f));
    return *reinterpret_cast<uint32_t*>(&h);
}
// warp-segmented max over the 8 lanes sharing (lane & 3); input must be >= 0
__device__ __forceinline__ uint32_t redux_max_seg4(uint32_t v, uint32_t mask) {
    uint32_t r;
    asm volatile("redux.sync.max.u32 %0, %1, %2;" : "=r"(r) : "r"(v), "r"(mask));
    return r;
}

// B stationed in smem rows [n x 72-stride]; GEMM over K=64, N=64
__device__ __forceinline__ void gemm64(uint32_t sbase, const uint32_t (&a)[4][4],
                                       float (&c)[8][4], int lane) {
#pragma unroll
    for (int j = 0; j < 8; j++)
#pragma unroll
        for (int r = 0; r < 4; r++) c[j][r] = 0.f;
#pragma unroll
    for (int q = 0; q < 4; q++) {
#pragma unroll
        for (int jp = 0; jp < 4; jp++) {
            uint32_t B0, B1, B2, B3;
            uint32_t bn = 16 * jp + (lane & 7) + 8 * (lane >> 4);
            uint32_t bk = q * 16 + 8 * ((lane >> 3) & 1);
            ldsm4(B0, B1, B2, B3, sbase + (bn * 72 + bk) * 2);
            mma_f16(c[2 * jp],     a[q][0], a[q][1], a[q][2], a[q][3], B0, B1);
            mma_f16(c[2 * jp + 1], a[q][0], a[q][1], a[q][2], a[q][3], B2, B3);
        }
    }
}
__device__ __forceinline__ void pack_relu(const float (&c)[8][4], uint32_t (&a)[4][4]) {
#pragma unroll
    for (int q = 0; q < 4; q++) {
        a[q][0] = ph2_relu(c[2 * q][0],     c[2 * q][1]);
        a[q][1] = ph2_relu(c[2 * q][2],     c[2 * q][3]);
        a[q][2] = ph2_relu(c[2 * q + 1][0], c[2 * q + 1][1]);
        a[q][3] = ph2_relu(c[2 * q + 1][2], c[2 * q + 1][3]);
    }
}

// ---------------- prep: w2..w5 fp32->fp16 + zero d_g (one kernel) ----------------
__global__ void __launch_bounds__(256) k_prep(const float* __restrict__ w2,
                                              const float* __restrict__ w3,
                                              const float* __restrict__ w4,
                                              const float* __restrict__ w5) {
    int b = blockIdx.x, t = threadIdx.x;
    if (b < 768) {
        int i = b * 256 + t;                       // 196608 w5 elements
        d_w5h[i] = __float2half_rn(w5[i]);
    } else if (b < 832) {
        int i = (b - 768) * 256 + t;               // 16384 w2/w3/w4 elements
        if (i < 4096)      d_w2h[i]        = __float2half_rn(w2[i]);
        else if (i < 8192) d_w3h[i - 4096] = __float2half_rn(w3[i - 4096]);
        else               d_w4h[i - 8192] = __float2half_rn(w4[i - 8192]);
    } else {
        d_g[(b - 832) * 256 + t] = 0.0f;           // 1024 (relu output >= 0)
    }
}

// ---------------- fused mlp1..mlp4 : x[N,3] -> h2[N,64], h4[N,128] ----------------
__global__ void __launch_bounds__(256, 2) k_mlp1234(const float* __restrict__ x,
                                                    const float* __restrict__ w1) {
    extern __shared__ __half sh[];
    const int OFF_W2 = 0, OFF_W3 = 4608, OFF_W4 = 9216, OFF_OUT = 18432;
    __half* s_out = sh + OFF_OUT;                   // 128*136
    float*  s_xf  = (float*)(sh + 35840);           // 128*3
    float*  s_w1f = s_xf + 384;                     // 64*3

    int t = threadIdx.x, lane = t & 31, w = t >> 5;
    int g = lane >> 2, tig = lane & 3;
    size_t p0 = (size_t)blockIdx.x * 128;
    uint32_t sb = smem_u32(sh);

    for (int i = t; i < 512; i += 256) {
        int r = i >> 3, c = i & 7;
        cp16(sb + (uint32_t)(OFF_W2 + r * 72 + c * 8) * 2, d_w2h + r * 64 + c * 8);
        cp16(sb + (uint32_t)(OFF_W3 + r * 72 + c * 8) * 2, d_w3h + r * 64 + c * 8);
    }
    for (int i = t; i < 1024; i += 256) {
        int r = i >> 3, c = i & 7;
        cp16(sb + (uint32_t)(OFF_W4 + r * 72 + c * 8) * 2, d_w4h + r * 64 + c * 8);
    }
    for (int i = t; i < 384; i += 256) s_xf[i] = x[p0 * 3 + i];
    if (t < 192) s_w1f[t] = w1[t];
    CP_COMMIT(); CP_WAIT0();
    __syncthreads();

    // mlp1: this thread's 32 h1 values straight into a-frag layout
    int r0 = 16 * w + g;
    float xa0 = s_xf[r0 * 3], xa1 = s_xf[r0 * 3 + 1], xa2 = s_xf[r0 * 3 + 2];
    float xb0 = s_xf[(r0 + 8) * 3], xb1 = s_xf[(r0 + 8) * 3 + 1], xb2 = s_xf[(r0 + 8) * 3 + 2];
    uint32_t a1h[4][4];
#pragma unroll
    for (int q = 0; q < 4; q++) {
        int f0 = 16 * q + 2 * tig;
        int f2 = f0 + 8;
#define DOT3(f, u0, u1, u2) \
        fmaf(s_w1f[(f)*3+2], u2, fmaf(s_w1f[(f)*3+1], u1, s_w1f[(f)*3] * u0))
        a1h[q][0] = ph2_relu(DOT3(f0, xa0, xa1, xa2), DOT3(f0 + 1, xa0, xa1, xa2));
        a1h[q][1] = ph2_relu(DOT3(f0, xb0, xb1, xb2), DOT3(f0 + 1, xb0, xb1, xb2));
        a1h[q][2] = ph2_relu(DOT3(f2, xa0, xa1, xa2), DOT3(f2 + 1, xa0, xa1, xa2));
        a1h[q][3] = ph2_relu(DOT3(f2, xb0, xb1, xb2), DOT3(f2 + 1, xb0, xb1, xb2));
#undef DOT3
    }

    // GEMM2: h2 = relu(h1 @ w2^T)
    float c2[8][4];
    uint32_t a2h[4][4];
    gemm64(sb + OFF_W2 * 2, a1h, c2, lane);
    pack_relu(c2, a2h);

#pragma unroll
    for (int q = 0; q < 4; q++) {
        int c0 = 16 * q + 2 * tig, cc2 = c0 + 8;
        *(uint32_t*)&s_out[r0 * 136 + c0]        = a2h[q][0];
        *(uint32_t*)&s_out[(r0 + 8) * 136 + c0]  = a2h[q][1];
        *(uint32_t*)&s_out[r0 * 136 + cc2]       = a2h[q][2];
        *(uint32_t*)&s_out[(r0 + 8) * 136 + cc2] = a2h[q][3];
    }
    __syncthreads();
    for (int i = t; i < 1024; i += 256) {
        int r = i >> 3, c = i & 7;
        *(uint4*)&d_h2h[(p0 + r) * 64 + c * 8] = *(uint4*)&s_out[r * 136 + c * 8];
    }
    __syncthreads();   // s_out reused for h4

    // GEMM3: h3 = relu(h2 @ w3^T)
    float c3[8][4];
    uint32_t a3h[4][4];
    gemm64(sb + OFF_W3 * 2, a2h, c3, lane);
    pack_relu(c3, a3h);

    // GEMM4: h4 = relu(h3 @ w4^T), N=128 in two halves
#pragma unroll
    for (int nh = 0; nh < 2; nh++) {
        float c4[8][4];
#pragma unroll
        for (int j = 0; j < 8; j++)
#pragma unroll
            for (int r = 0; r < 4; r++) c4[j][r] = 0.f;
#pragma unroll
        for (int q = 0; q < 4; q++) {
#pragma unroll
            for (int jp = 0; jp < 4; jp++) {
                uint32_t B0, B1, B2, B3;
                uint32_t bn = 64 * nh + 16 * jp + (lane & 7) + 8 * (lane >> 4);
                uint32_t bk = q * 16 + 8 * ((lane >> 3) & 1);
                ldsm4(B0, B1, B2, B3, sb + (OFF_W4 + bn * 72 + bk) * 2);
                mma_f16(c4[2 * jp],     a3h[q][0], a3h[q][1], a3h[q][2], a3h[q][3], B0, B1);
                mma_f16(c4[2 * jp + 1], a3h[q][0], a3h[q][1], a3h[q][2], a3h[q][3], B2, B3);
            }
        }
#pragma unroll
        for (int j2 = 0; j2 < 8; j2++) {
            int coln = 64 * nh + 8 * j2 + 2 * tig;
            *(uint32_t*)&s_out[r0 * 136 + coln]       = ph2_relu(c4[j2][0], c4[j2][1]);
            *(uint32_t*)&s_out[(r0 + 8) * 136 + coln] = ph2_relu(c4[j2][2], c4[j2][3]);
        }
    }
    __syncthreads();
    for (int i = t; i < 2048; i += 256) {
        int r = i >> 4, c = i & 15;
        *(uint4*)&d_h4h[(p0 + r) * 128 + c * 8] = *(uint4*)&s_out[r * 136 + c * 8];
    }
}

// ---------------- graph max pooling (K=16), fp16, 32 threads/point ----------------
__global__ void __launch_bounds__(256) k_gmax(const int* __restrict__ indices) {
    __shared__ int s_idx[8][16];
    int t = threadIdx.x, lane = t & 31, pl = t >> 5;
    int base = blockIdx.x * 8;
    if (t < 128) s_idx[t >> 4][t & 15] = indices[base * 16 + t];
    __syncthreads();

    __half2 m = __float2half2_rn(0.0f);   // h2 >= 0
    const __half2* h2 = (const __half2*)d_h2h;
#pragma unroll
    for (int j = 0; j < 16; j++) {
        unsigned off = (unsigned)s_idx[pl][j] * 32u + (unsigned)lane;
        m = __hmax2(m, h2[off]);
    }
    ((__half2*)d_xgmh)[(unsigned)(base + pl) * 32u + lane] = m;
}

// ---------------- mlp5 + global max : 128-row blocks, 2 CTAs/SM ----------------
// Round-9 structure (best known). Epilogue: per-warp col-max via mt-tree, relu,
// then warp-segmented redux.sync.max.u32 (valid since values are >= 0), then
// atomicMax into d_g from lanes 0..3.
__global__ void __launch_bounds__(256, 2) k_mlp5max() {
    extern __shared__ __half sh5[];
    __half* s_a = sh5;                        // 128*200
    __half* s_b = sh5 + 25600;                // 128*200

    int t = threadIdx.x, lane = t & 31, w = t >> 5;
    int wm = w >> 2, wn = w & 3;
    size_t m0 = (size_t)blockIdx.x * 128;
    uint32_t ab = smem_u32(s_a), bb = smem_u32(s_b);
    uint32_t rmask = 0x11111111u << (lane & 3);

    // stage A (once) + B tile 0
    for (int i = t; i < 3072; i += 256) {
        int r = i / 24, c = i % 24;
        const __half* src = (c < 8) ? d_xgmh + (m0 + r) * 64 + c * 8
                                    : d_h4h + (m0 + r) * 128 + (c - 8) * 8;
        cp16(ab + (uint32_t)(r * 200 + c * 8) * 2, src);
    }
    for (int i = t; i < 3072; i += 256) {
        int r = i / 24, c = i % 24;
        cp16(bb + (uint32_t)(r * 200 + c * 8) * 2, d_w5h + (size_t)r * 192 + c * 8);
    }
    CP_COMMIT(); CP_WAIT0();
    __syncthreads();

    for (int nt = 0; nt < 8; nt++) {
        float c_[4][4][4];
#pragma unroll
        for (int i = 0; i < 4; i++)
#pragma unroll
            for (int j = 0; j < 4; j++)
#pragma unroll
                for (int r = 0; r < 4; r++) c_[i][j][r] = 0.f;

#pragma unroll
        for (int q = 0; q < 12; q++) {
            uint32_t a_[4][4], b_[2][4];
#pragma unroll
            for (int mt = 0; mt < 4; mt++) {
                uint32_t row = 64 * wm + 16 * mt + (lane & 15);
                uint32_t kh  = q * 16 + 8 * (lane >> 4);
                ldsm4(a_[mt][0], a_[mt][1], a_[mt][2], a_[mt][3],
                      ab + (row * 200 + kh) * 2);
            }
#pragma unroll
            for (int p = 0; p < 2; p++) {
                uint32_t bn = 32 * wn + 16 * p + (lane & 7) + 8 * (lane >> 4);
                uint32_t kh = q * 16 + 8 * ((lane >> 3) & 1);
                ldsm4(b_[p][0], b_[p][1], b_[p][2], b_[p][3],
                      bb + (bn * 200 + kh) * 2);
            }
#pragma unroll
            for (int mt = 0; mt < 4; mt++) {
                mma_f16(c_[mt][0], a_[mt][0], a_[mt][1], a_[mt][2], a_[mt][3], b_[0][0], b_[0][1]);
                mma_f16(c_[mt][1], a_[mt][0], a_[mt][1], a_[mt][2], a_[mt][3], b_[0][2], b_[0][3]);
                mma_f16(c_[mt][2], a_[mt][0], a_[mt][1], a_[mt][2], a_[mt][3], b_[1][0], b_[1][1]);
                mma_f16(c_[mt][3], a_[mt][0], a_[mt][1], a_[mt][2], a_[mt][3], b_[1][2], b_[1][3]);
            }
        }
        __syncthreads();     // all warps done reading s_b

        if (nt < 7) {        // prefetch next B tile; overlaps epilogue
            for (int i = t; i < 3072; i += 256) {
                int r = i / 24, c = i % 24;
                cp16(bb + (uint32_t)(r * 200 + c * 8) * 2,
                     d_w5h + (size_t)((nt + 1) * 128 + r) * 192 + c * 8);
            }
            CP_COMMIT();
        }

        // epilogue: mt-tree col-max (4 rows-of-lane), relu, warp-segmented redux,
        // atomicMax into d_g
        uint32_t cu[8];
#pragma unroll
        for (int nq = 0; nq < 4; nq++) {
            float v0 = fmaxf(fmaxf(c_[0][nq][0], c_[0][nq][2]),
                             fmaxf(c_[1][nq][0], c_[1][nq][2]));
            v0 = fmaxf(v0, fmaxf(fmaxf(c_[2][nq][0], c_[2][nq][2]),
                                 fmaxf(c_[3][nq][0], c_[3][nq][2])));
            float v1 = fmaxf(fmaxf(c_[0][nq][1], c_[0][nq][3]),
                             fmaxf(c_[1][nq][1], c_[1][nq][3]));
            v1 = fmaxf(v1, fmaxf(fmaxf(c_[2][nq][1], c_[2][nq][3]),
                                 fmaxf(c_[3][nq][1], c_[3][nq][3])));
            cu[nq * 2 + 0] = __float_as_uint(fmaxf(v0, 0.0f));   // >= 0: uint order ok
            cu[nq * 2 + 1] = __float_as_uint(fmaxf(v1, 0.0f));
        }
#pragma unroll
        for (int j = 0; j < 8; j++)
            cu[j] = redux_max_seg4(cu[j], rmask);
        if (lane < 4) {
            int colbase = nt * 128 + wn * 32 + 2 * lane;
#pragma unroll
            for (int nq = 0; nq < 4; nq++) {
                atomicMax((int*)&d_g[colbase + nq * 8],     (int)cu[2 * nq]);
                atomicMax((int*)&d_g[colbase + nq * 8 + 1], (int)cu[2 * nq + 1]);
            }
        }
        if (nt < 7) CP_WAIT0();
        __syncthreads();     // s_b refilled, safe for next iteration
    }
}

// ---------------- head: 3 small GEMVs ----------------
__device__ __forceinline__ float blk_dot_reduce(float a) {
#pragma unroll
    for (int o = 16; o; o >>= 1) a += __shfl_xor_sync(0xffffffffu, a, o);
    __shared__ float s[4];
    int t = threadIdx.x;
    if ((t & 31) == 0) s[t >> 5] = a;
    __syncthreads();
    return s[0] + s[1] + s[2] + s[3];
}

__global__ void __launch_bounds__(128) k_head1(const float* __restrict__ wf1) {
    int t = threadIdx.x;
    const float4* wr = (const float4*)&wf1[(size_t)blockIdx.x * 1024];
    const float4* gr = (const float4*)d_g;
    float a = 0.f;
    for (int k = t; k < 256; k += 128) {
        float4 wv = __ldg(&wr[k]); float4 gv = gr[k];
        a += wv.x * gv.x + wv.y * gv.y + wv.z * gv.z + wv.w * gv.w;
    }
    float r = blk_dot_reduce(a);
    if (t == 0) d_f1[blockIdx.x] = fmaxf(r, 0.0f);
}

__global__ void __launch_bounds__(128) k_head2(const float* __restrict__ wf2) {
    int t = threadIdx.x;
    const float4* wr = (const float4*)&wf2[(size_t)blockIdx.x * 512];
    const float4* gr = (const float4*)d_f1;
    float a = 0.f;
    if (t < 128) {
        float4 wv = __ldg(&wr[t]); float4 gv = gr[t];
        a = wv.x * gv.x + wv.y * gv.y + wv.z * gv.z + wv.w * gv.w;
    }
    float r = blk_dot_reduce(a);
    if (t == 0) d_f2[blockIdx.x] = fmaxf(r, 0.0f);
}

__global__ void __launch_bounds__(128) k_head3(const float* __restrict__ wf3,
                                               float* __restrict__ out) {
    int t = threadIdx.x;
    const float4* wr = (const float4*)&wf3[(size_t)blockIdx.x * 256];
    const float4* gr = (const float4*)d_f2;
    float a = 0.f;
    if (t < 64) {
        float4 wv = __ldg(&wr[t]); float4 gv = gr[t];
        a = wv.x * gv.x + wv.y * gv.y + wv.z * gv.z + wv.w * gv.w;
    }
    float r = blk_dot_reduce(a);
    if (t == 0) out[blockIdx.x] = r;
}

// ---------------- launch ----------------
extern "C" void kernel_launch(void* const* d_in, const int* in_sizes, int n_in,
                              void* d_out, int out_size) {
    const float* x       = (const float*)d_in[0];
    const int*   indices = (const int*)d_in[2];   // indptr (d_in[1]) fixed K=16
    const float* w1  = (const float*)d_in[3];
    const float* w2  = (const float*)d_in[4];
    const float* w3  = (const float*)d_in[5];
    const float* w4  = (const float*)d_in[6];
    const float* w5  = (const float*)d_in[7];
    const float* wf1 = (const float*)d_in[8];
    const float* wf2 = (const float*)d_in[9];
    const float* wf3 = (const float*)d_in[10];
    float* out = (float*)d_out;

    const int SMEM_F = 35840 * 2 + 576 * 4;           // 74,176 B
    const int SMEM_5 = 2 * 128 * 200 * 2;             // 102,400 B -> 2 CTAs/SM
    cudaFuncSetAttribute(k_mlp1234, cudaFuncAttributeMaxDynamicSharedMemorySize, SMEM_F);
    cudaFuncSetAttribute(k_mlp5max, cudaFuncAttributeMaxDynamicSharedMemorySize, SMEM_5);

    k_prep   <<<836, 256>>>(w2, w3, w4, w5);
    k_mlp1234<<<NPTS / 128, 256, SMEM_F>>>(x, w1);
    k_gmax   <<<NPTS / 8,   256>>>(indices);
    k_mlp5max<<<NPTS / 128, 256, SMEM_5>>>();
    k_head1  <<<512, 128>>>(wf1);
    k_head2  <<<256, 128>>>(wf2);
    k_head3  <<<40,  128>>>(wf3, out);
}

// round 15
// speedup vs baseline: 1.1724x; 1.1724x over previous
#include <cuda_runtime.h>
#include <cuda_fp16.h>
#include <cstdint>

#define NPTS 262144

// ---------------- device scratch (no allocations allowed) ----------------
__device__ __half d_h2h [NPTS * 64];      // after mlp1+mlp2 (relu, fp16)
__device__ __half d_xgmh[NPTS * 64];      // neighbor max-pooled (fp16)
__device__ __half d_h4h [NPTS * 128];     // after mlp3+mlp4 (relu, fp16)
__device__ __half d_w2h [64 * 64];
__device__ __half d_w3h [64 * 64];
__device__ __half d_w4h [128 * 64];
__device__ __half d_w5h [1024 * 192];
__device__ float  d_g  [1024];            // global max (post-relu), atomicMax target
__device__ float  d_f1 [512];
__device__ float  d_f2 [256];

// ---------------- helpers ----------------
__device__ __forceinline__ uint32_t smem_u32(const void* p) {
    uint32_t a;
    asm("{ .reg .u64 t; cvta.to.shared.u64 t, %1; cvt.u32.u64 %0, t; }"
        : "=r"(a) : "l"(p));
    return a;
}
__device__ __forceinline__ void cp16(uint32_t dst, const void* src) {
    asm volatile("cp.async.cg.shared.global [%0], [%1], 16;"
                 :: "r"(dst), "l"(src) : "memory");
}
#define CP_COMMIT() asm volatile("cp.async.commit_group;" ::: "memory")
#define CP_WAIT0()  asm volatile("cp.async.wait_group 0;" ::: "memory")

__device__ __forceinline__ void ldsm4(uint32_t& r0, uint32_t& r1,
                                      uint32_t& r2, uint32_t& r3, uint32_t addr) {
    asm volatile("ldmatrix.sync.aligned.m8n8.x4.shared.b16 {%0,%1,%2,%3}, [%4];"
                 : "=r"(r0), "=r"(r1), "=r"(r2), "=r"(r3) : "r"(addr));
}
__device__ __forceinline__ void mma_f16(float* c, uint32_t a0, uint32_t a1,
                                        uint32_t a2, uint32_t a3,
                                        uint32_t b0, uint32_t b1) {
    asm volatile(
        "mma.sync.aligned.m16n8k16.row.col.f32.f16.f16.f32 "
        "{%0,%1,%2,%3}, {%4,%5,%6,%7}, {%8,%9}, {%0,%1,%2,%3};"
        : "+f"(c[0]), "+f"(c[1]), "+f"(c[2]), "+f"(c[3])
        : "r"(a0), "r"(a1), "r"(a2), "r"(a3), "r"(b0), "r"(b1));
}
__device__ __forceinline__ uint32_t ph2_relu(float x, float y) {
    __half2 h = __floats2half2_rn(fmaxf(x, 0.f), fmaxf(y, 0.f));
    return *reinterpret_cast<uint32_t*>(&h);
}

// B stationed in smem rows [n x 72-stride]; GEMM over K=64, N=64
__device__ __forceinline__ void gemm64(uint32_t sbase, const uint32_t (&a)[4][4],
                                       float (&c)[8][4], int lane) {
#pragma unroll
    for (int j = 0; j < 8; j++)
#pragma unroll
        for (int r = 0; r < 4; r++) c[j][r] = 0.f;
#pragma unroll
    for (int q = 0; q < 4; q++) {
#pragma unroll
        for (int jp = 0; jp < 4; jp++) {
            uint32_t B0, B1, B2, B3;
            uint32_t bn = 16 * jp + (lane & 7) + 8 * (lane >> 4);
            uint32_t bk = q * 16 + 8 * ((lane >> 3) & 1);
            ldsm4(B0, B1, B2, B3, sbase + (bn * 72 + bk) * 2);
            mma_f16(c[2 * jp],     a[q][0], a[q][1], a[q][2], a[q][3], B0, B1);
            mma_f16(c[2 * jp + 1], a[q][0], a[q][1], a[q][2], a[q][3], B2, B3);
        }
    }
}
__device__ __forceinline__ void pack_relu(const float (&c)[8][4], uint32_t (&a)[4][4]) {
#pragma unroll
    for (int q = 0; q < 4; q++) {
        a[q][0] = ph2_relu(c[2 * q][0],     c[2 * q][1]);
        a[q][1] = ph2_relu(c[2 * q][2],     c[2 * q][3]);
        a[q][2] = ph2_relu(c[2 * q + 1][0], c[2 * q + 1][1]);
        a[q][3] = ph2_relu(c[2 * q + 1][2], c[2 * q + 1][3]);
    }
}

// ---------------- prep: w2..w5 fp32->fp16 + zero d_g (one kernel) ----------------
__global__ void __launch_bounds__(256) k_prep(const float* __restrict__ w2,
                                              const float* __restrict__ w3,
                                              const float* __restrict__ w4,
                                              const float* __restrict__ w5) {
    int b = blockIdx.x, t = threadIdx.x;
    if (b < 768) {
        int i = b * 256 + t;                       // 196608 w5 elements
        d_w5h[i] = __float2half_rn(w5[i]);
    } else if (b < 832) {
        int i = (b - 768) * 256 + t;               // 16384 w2/w3/w4 elements
        if (i < 4096)      d_w2h[i]        = __float2half_rn(w2[i]);
        else if (i < 8192) d_w3h[i - 4096] = __float2half_rn(w3[i - 4096]);
        else               d_w4h[i - 8192] = __float2half_rn(w4[i - 8192]);
    } else {
        d_g[(b - 832) * 256 + t] = 0.0f;           // 1024 (relu output >= 0)
    }
}

// ---------------- fused mlp1..mlp4 : x[N,3] -> h2[N,64], h4[N,128] ----------------
__global__ void __launch_bounds__(256, 2) k_mlp1234(const float* __restrict__ x,
                                                    const float* __restrict__ w1) {
    extern __shared__ __half sh[];
    const int OFF_W2 = 0, OFF_W3 = 4608, OFF_W4 = 9216, OFF_OUT = 18432;
    __half* s_out = sh + OFF_OUT;                   // 128*136
    float*  s_xf  = (float*)(sh + 35840);           // 128*3
    float*  s_w1f = s_xf + 384;                     // 64*3

    int t = threadIdx.x, lane = t & 31, w = t >> 5;
    int g = lane >> 2, tig = lane & 3;
    size_t p0 = (size_t)blockIdx.x * 128;
    uint32_t sb = smem_u32(sh);

    for (int i = t; i < 512; i += 256) {
        int r = i >> 3, c = i & 7;
        cp16(sb + (uint32_t)(OFF_W2 + r * 72 + c * 8) * 2, d_w2h + r * 64 + c * 8);
        cp16(sb + (uint32_t)(OFF_W3 + r * 72 + c * 8) * 2, d_w3h + r * 64 + c * 8);
    }
    for (int i = t; i < 1024; i += 256) {
        int r = i >> 3, c = i & 7;
        cp16(sb + (uint32_t)(OFF_W4 + r * 72 + c * 8) * 2, d_w4h + r * 64 + c * 8);
    }
    for (int i = t; i < 384; i += 256) s_xf[i] = x[p0 * 3 + i];
    if (t < 192) s_w1f[t] = w1[t];
    CP_COMMIT(); CP_WAIT0();
    __syncthreads();

    // mlp1: this thread's 32 h1 values straight into a-frag layout
    int r0 = 16 * w + g;
    float xa0 = s_xf[r0 * 3], xa1 = s_xf[r0 * 3 + 1], xa2 = s_xf[r0 * 3 + 2];
    float xb0 = s_xf[(r0 + 8) * 3], xb1 = s_xf[(r0 + 8) * 3 + 1], xb2 = s_xf[(r0 + 8) * 3 + 2];
    uint32_t a1h[4][4];
#pragma unroll
    for (int q = 0; q < 4; q++) {
        int f0 = 16 * q + 2 * tig;
        int f2 = f0 + 8;
#define DOT3(f, u0, u1, u2) \
        fmaf(s_w1f[(f)*3+2], u2, fmaf(s_w1f[(f)*3+1], u1, s_w1f[(f)*3] * u0))
        a1h[q][0] = ph2_relu(DOT3(f0, xa0, xa1, xa2), DOT3(f0 + 1, xa0, xa1, xa2));
        a1h[q][1] = ph2_relu(DOT3(f0, xb0, xb1, xb2), DOT3(f0 + 1, xb0, xb1, xb2));
        a1h[q][2] = ph2_relu(DOT3(f2, xa0, xa1, xa2), DOT3(f2 + 1, xa0, xa1, xa2));
        a1h[q][3] = ph2_relu(DOT3(f2, xb0, xb1, xb2), DOT3(f2 + 1, xb0, xb1, xb2));
#undef DOT3
    }

    // GEMM2: h2 = relu(h1 @ w2^T)
    float c2[8][4];
    uint32_t a2h[4][4];
    gemm64(sb + OFF_W2 * 2, a1h, c2, lane);
    pack_relu(c2, a2h);

#pragma unroll
    for (int q = 0; q < 4; q++) {
        int c0 = 16 * q + 2 * tig, cc2 = c0 + 8;
        *(uint32_t*)&s_out[r0 * 136 + c0]        = a2h[q][0];
        *(uint32_t*)&s_out[(r0 + 8) * 136 + c0]  = a2h[q][1];
        *(uint32_t*)&s_out[r0 * 136 + cc2]       = a2h[q][2];
        *(uint32_t*)&s_out[(r0 + 8) * 136 + cc2] = a2h[q][3];
    }
    __syncthreads();
    for (int i = t; i < 1024; i += 256) {
        int r = i >> 3, c = i & 7;
        *(uint4*)&d_h2h[(p0 + r) * 64 + c * 8] = *(uint4*)&s_out[r * 136 + c * 8];
    }
    __syncthreads();   // s_out reused for h4

    // GEMM3: h3 = relu(h2 @ w3^T)
    float c3[8][4];
    uint32_t a3h[4][4];
    gemm64(sb + OFF_W3 * 2, a2h, c3, lane);
    pack_relu(c3, a3h);

    // GEMM4: h4 = relu(h3 @ w4^T), N=128 in two halves
#pragma unroll
    for (int nh = 0; nh < 2; nh++) {
        float c4[8][4];
#pragma unroll
        for (int j = 0; j < 8; j++)
#pragma unroll
            for (int r = 0; r < 4; r++) c4[j][r] = 0.f;
#pragma unroll
        for (int q = 0; q < 4; q++) {
#pragma unroll
            for (int jp = 0; jp < 4; jp++) {
                uint32_t B0, B1, B2, B3;
                uint32_t bn = 64 * nh + 16 * jp + (lane & 7) + 8 * (lane >> 4);
                uint32_t bk = q * 16 + 8 * ((lane >> 3) & 1);
                ldsm4(B0, B1, B2, B3, sb + (OFF_W4 + bn * 72 + bk) * 2);
                mma_f16(c4[2 * jp],     a3h[q][0], a3h[q][1], a3h[q][2], a3h[q][3], B0, B1);
                mma_f16(c4[2 * jp + 1], a3h[q][0], a3h[q][1], a3h[q][2], a3h[q][3], B2, B3);
            }
        }
#pragma unroll
        for (int j2 = 0; j2 < 8; j2++) {
            int coln = 64 * nh + 8 * j2 + 2 * tig;
            *(uint32_t*)&s_out[r0 * 136 + coln]       = ph2_relu(c4[j2][0], c4[j2][1]);
            *(uint32_t*)&s_out[(r0 + 8) * 136 + coln] = ph2_relu(c4[j2][2], c4[j2][3]);
        }
    }
    __syncthreads();
    for (int i = t; i < 2048; i += 256) {
        int r = i >> 4, c = i & 15;
        *(uint4*)&d_h4h[(p0 + r) * 128 + c * 8] = *(uint4*)&s_out[r * 136 + c * 8];
    }
}

// ---------------- graph max pooling (K=16), fp16, 32 threads/point ----------------
__global__ void __launch_bounds__(256) k_gmax(const int* __restrict__ indices) {
    __shared__ int s_idx[8][16];
    int t = threadIdx.x, lane = t & 31, pl = t >> 5;
    int base = blockIdx.x * 8;
    if (t < 128) s_idx[t >> 4][t & 15] = indices[base * 16 + t];
    __syncthreads();

    __half2 m = __float2half2_rn(0.0f);   // h2 >= 0
    const __half2* h2 = (const __half2*)d_h2h;
#pragma unroll
    for (int j = 0; j < 16; j++) {
        unsigned off = (unsigned)s_idx[pl][j] * 32u + (unsigned)lane;
        m = __hmax2(m, h2[off]);
    }
    ((__half2*)d_xgmh)[(unsigned)(base + pl) * 32u + lane] = m;
}

// ---------------- mlp5 + global max : 128-row blocks, 2 CTAs/SM ----------------
// Verified round-9 structure (best measured: 269us, tensor 62.6%).
// Epilogue: warp shfl col-max -> relu -> atomicMax into d_g.
__global__ void __launch_bounds__(256, 2) k_mlp5max() {
    extern __shared__ __half sh5[];
    __half* s_a = sh5;                        // 128*200
    __half* s_b = sh5 + 25600;                // 128*200

    int t = threadIdx.x, lane = t & 31, w = t >> 5;
    int wm = w >> 2, wn = w & 3;
    size_t m0 = (size_t)blockIdx.x * 128;
    uint32_t ab = smem_u32(s_a), bb = smem_u32(s_b);

    // stage A (once) + B tile 0
    for (int i = t; i < 3072; i += 256) {
        int r = i / 24, c = i % 24;
        const __half* src = (c < 8) ? d_xgmh + (m0 + r) * 64 + c * 8
                                    : d_h4h + (m0 + r) * 128 + (c - 8) * 8;
        cp16(ab + (uint32_t)(r * 200 + c * 8) * 2, src);
    }
    for (int i = t; i < 3072; i += 256) {
        int r = i / 24, c = i % 24;
        cp16(bb + (uint32_t)(r * 200 + c * 8) * 2, d_w5h + (size_t)r * 192 + c * 8);
    }
    CP_COMMIT(); CP_WAIT0();
    __syncthreads();

    for (int nt = 0; nt < 8; nt++) {
        float c_[4][4][4];
#pragma unroll
        for (int i = 0; i < 4; i++)
#pragma unroll
            for (int j = 0; j < 4; j++)
#pragma unroll
                for (int r = 0; r < 4; r++) c_[i][j][r] = 0.f;

#pragma unroll
        for (int q = 0; q < 12; q++) {
            uint32_t a_[4][4], b_[2][4];
#pragma unroll
            for (int mt = 0; mt < 4; mt++) {
                uint32_t row = 64 * wm + 16 * mt + (lane & 15);
                uint32_t kh  = q * 16 + 8 * (lane >> 4);
                ldsm4(a_[mt][0], a_[mt][1], a_[mt][2], a_[mt][3],
                      ab + (row * 200 + kh) * 2);
            }
#pragma unroll
            for (int p = 0; p < 2; p++) {
                uint32_t bn = 32 * wn + 16 * p + (lane & 7) + 8 * (lane >> 4);
                uint32_t kh = q * 16 + 8 * ((lane >> 3) & 1);
                ldsm4(b_[p][0], b_[p][1], b_[p][2], b_[p][3],
                      bb + (bn * 200 + kh) * 2);
            }
#pragma unroll
            for (int mt = 0; mt < 4; mt++) {
                mma_f16(c_[mt][0], a_[mt][0], a_[mt][1], a_[mt][2], a_[mt][3], b_[0][0], b_[0][1]);
                mma_f16(c_[mt][1], a_[mt][0], a_[mt][1], a_[mt][2], a_[mt][3], b_[0][2], b_[0][3]);
                mma_f16(c_[mt][2], a_[mt][0], a_[mt][1], a_[mt][2], a_[mt][3], b_[1][0], b_[1][1]);
                mma_f16(c_[mt][3], a_[mt][0], a_[mt][1], a_[mt][2], a_[mt][3], b_[1][2], b_[1][3]);
            }
        }
        __syncthreads();     // all warps done reading s_b

        if (nt < 7) {        // prefetch next B tile; overlaps epilogue
            for (int i = t; i < 3072; i += 256) {
                int r = i / 24, c = i % 24;
                cp16(bb + (uint32_t)(r * 200 + c * 8) * 2,
                     d_w5h + (size_t)((nt + 1) * 128 + r) * 192 + c * 8);
            }
            CP_COMMIT();
        }

        // epilogue: col-max over warp's 64 rows, relu, atomicMax into d_g
        float cm[8];
#pragma unroll
        for (int nq = 0; nq < 4; nq++) {
            float v0 = fmaxf(fmaxf(c_[0][nq][0], c_[0][nq][2]),
                             fmaxf(c_[1][nq][0], c_[1][nq][2]));
            v0 = fmaxf(v0, fmaxf(fmaxf(c_[2][nq][0], c_[2][nq][2]),
                                 fmaxf(c_[3][nq][0], c_[3][nq][2])));
            float v1 = fmaxf(fmaxf(c_[0][nq][1], c_[0][nq][3]),
                             fmaxf(c_[1][nq][1], c_[1][nq][3]));
            v1 = fmaxf(v1, fmaxf(fmaxf(c_[2][nq][1], c_[2][nq][3]),
                                 fmaxf(c_[3][nq][1], c_[3][nq][3])));
            cm[nq * 2 + 0] = v0;
            cm[nq * 2 + 1] = v1;
        }
#pragma unroll
        for (int off = 4; off < 32; off <<= 1)
#pragma unroll
            for (int j = 0; j < 8; j++)
                cm[j] = fmaxf(cm[j], __shfl_xor_sync(0xffffffffu, cm[j], off));
        if (lane < 4) {
            int colbase = nt * 128 + wn * 32 + 2 * lane;
#pragma unroll
            for (int nq = 0; nq < 4; nq++) {
                atomicMax((int*)&d_g[colbase + nq * 8],
                          __float_as_int(fmaxf(cm[2 * nq], 0.0f)));
                atomicMax((int*)&d_g[colbase + nq * 8 + 1],
                          __float_as_int(fmaxf(cm[2 * nq + 1], 0.0f)));
            }
        }
        if (nt < 7) CP_WAIT0();
        __syncthreads();     // s_b refilled, safe for next iteration
    }
}

// ---------------- head: 3 small GEMVs ----------------
__device__ __forceinline__ float blk_dot_reduce(float a) {
#pragma unroll
    for (int o = 16; o; o >>= 1) a += __shfl_xor_sync(0xffffffffu, a, o);
    __shared__ float s[4];
    int t = threadIdx.x;
    if ((t & 31) == 0) s[t >> 5] = a;
    __syncthreads();
    return s[0] + s[1] + s[2] + s[3];
}

__global__ void __launch_bounds__(128) k_head1(const float* __restrict__ wf1) {
    int t = threadIdx.x;
    const float4* wr = (const float4*)&wf1[(size_t)blockIdx.x * 1024];
    const float4* gr = (const float4*)d_g;
    float a = 0.f;
    for (int k = t; k < 256; k += 128) {
        float4 wv = __ldg(&wr[k]); float4 gv = gr[k];
        a += wv.x * gv.x + wv.y * gv.y + wv.z * gv.z + wv.w * gv.w;
    }
    float r = blk_dot_reduce(a);
    if (t == 0) d_f1[blockIdx.x] = fmaxf(r, 0.0f);
}

__global__ void __launch_bounds__(128) k_head2(const float* __restrict__ wf2) {
    int t = threadIdx.x;
    const float4* wr = (const float4*)&wf2[(size_t)blockIdx.x * 512];
    const float4* gr = (const float4*)d_f1;
    float a = 0.f;
    if (t < 128) {
        float4 wv = __ldg(&wr[t]); float4 gv = gr[t];
        a = wv.x * gv.x + wv.y * gv.y + wv.z * gv.z + wv.w * gv.w;
    }
    float r = blk_dot_reduce(a);
    if (t == 0) d_f2[blockIdx.x] = fmaxf(r, 0.0f);
}

__global__ void __launch_bounds__(128) k_head3(const float* __restrict__ wf3,
                                               float* __restrict__ out) {
    int t = threadIdx.x;
    const float4* wr = (const float4*)&wf3[(size_t)blockIdx.x * 256];
    const float4* gr = (const float4*)d_f2;
    float a = 0.f;
    if (t < 64) {
        float4 wv = __ldg(&wr[t]); float4 gv = gr[t];
        a = wv.x * gv.x + wv.y * gv.y + wv.z * gv.z + wv.w * gv.w;
    }
    float r = blk_dot_reduce(a);
    if (t == 0) out[blockIdx.x] = r;
}

// ---------------- launch ----------------
extern "C" void kernel_launch(void* const* d_in, const int* in_sizes, int n_in,
                              void* d_out, int out_size) {
    const float* x       = (const float*)d_in[0];
    const int*   indices = (const int*)d_in[2];   // indptr (d_in[1]) fixed K=16
    const float* w1  = (const float*)d_in[3];
    const float* w2  = (const float*)d_in[4];
    const float* w3  = (const float*)d_in[5];
    const float* w4  = (const float*)d_in[6];
    const float* w5  = (const float*)d_in[7];
    const float* wf1 = (const float*)d_in[8];
    const float* wf2 = (const float*)d_in[9];
    const float* wf3 = (const float*)d_in[10];
    float* out = (float*)d_out;

    const int SMEM_F = 35840 * 2 + 576 * 4;           // 74,176 B
    const int SMEM_5 = 2 * 128 * 200 * 2;             // 102,400 B -> 2 CTAs/SM
    cudaFuncSetAttribute(k_mlp1234, cudaFuncAttributeMaxDynamicSharedMemorySize, SMEM_F);
    cudaFuncSetAttribute(k_mlp5max, cudaFuncAttributeMaxDynamicSharedMemorySize, SMEM_5);

    k_prep   <<<836, 256>>>(w2, w3, w4, w5);
    k_mlp1234<<<NPTS / 128, 256, SMEM_F>>>(x, w1);
    k_gmax   <<<NPTS / 8,   256>>>(indices);
    k_mlp5max<<<NPTS / 128, 256, SMEM_5>>>();
    k_head1  <<<512, 128>>>(wf1);
    k_head2  <<<256, 128>>>(wf2);
    k_head3  <<<40,  128>>>(wf3, out);
}